// round 5
// baseline (speedup 1.0000x reference)
#include <cuda_runtime.h>
#include <math.h>

#define BATCH 2
#define SEQ 2048
#define DM 1024
#define NH 16
#define DH 64
#define MTOT (BATCH * SEQ)   // 4096

// Scratch (allocation-free rule: __device__ globals)
__device__ float g_q[BATCH * NH * SEQ * DH];     // [bh][s][d]
__device__ float g_k[BATCH * NH * SEQ * DH];
__device__ float g_v[BATCH * NH * SEQ * DH];
__device__ float g_attn[BATCH * SEQ * DM];       // [b][s][h*64+d]

// ---------------------------------------------------------------------------
// NT GEMM: C[m,n] = sum_k A[m,k] * W[n,k]   (M=4096, N=K=1024)
// mode 0: plain row-major write to Cout (output projection, A = g_attn)
// mode 1: headed layout + RoPE (Q / K), dst selected by `which`
// mode 2: headed layout, no RoPE (V)
// Tiles: BM=BN=128, BK=16, 256 threads, 8x8 per thread.
// ---------------------------------------------------------------------------
__global__ __launch_bounds__(256) void gemm_nt_kernel(
    const float* __restrict__ A, const float* __restrict__ W,
    const int* __restrict__ pos, float* __restrict__ Cout,
    int mode, int which)
{
    __shared__ float As[16][132];   // [k][m], padded
    __shared__ float Bs[16][132];   // [k][n], padded

    const int tid = threadIdx.x;
    const int tx = tid & 15;
    const int ty = tid >> 4;
    const int bx = blockIdx.x;      // N tile (8)
    const int by = blockIdx.y;      // M tile (32)

    const float* Ain = (mode == 0) ? g_attn : A;
    const int aRow = by * 128;
    const int bRow = bx * 128;

    float acc[8][8];
#pragma unroll
    for (int i = 0; i < 8; i++)
#pragma unroll
        for (int j = 0; j < 8; j++) acc[i][j] = 0.0f;

    for (int k0 = 0; k0 < DM; k0 += 16) {
#pragma unroll
        for (int j = 0; j < 2; j++) {
            int f = tid + j * 256;          // 512 float4 per operand tile
            int mr = f >> 2;                // 0..127
            int kq = (f & 3) << 2;          // 0,4,8,12
            float4 av = *(const float4*)&Ain[(size_t)(aRow + mr) * DM + k0 + kq];
            As[kq + 0][mr] = av.x; As[kq + 1][mr] = av.y;
            As[kq + 2][mr] = av.z; As[kq + 3][mr] = av.w;
            float4 wv = *(const float4*)&W[(size_t)(bRow + mr) * DM + k0 + kq];
            Bs[kq + 0][mr] = wv.x; Bs[kq + 1][mr] = wv.y;
            Bs[kq + 2][mr] = wv.z; Bs[kq + 3][mr] = wv.w;
        }
        __syncthreads();

#pragma unroll
        for (int kk = 0; kk < 16; kk++) {
            float4 a0 = *(const float4*)&As[kk][ty * 8];
            float4 a1 = *(const float4*)&As[kk][ty * 8 + 4];
            float4 b0 = *(const float4*)&Bs[kk][tx * 8];
            float4 b1 = *(const float4*)&Bs[kk][tx * 8 + 4];
            float a[8] = {a0.x, a0.y, a0.z, a0.w, a1.x, a1.y, a1.z, a1.w};
            float b[8] = {b0.x, b0.y, b0.z, b0.w, b1.x, b1.y, b1.z, b1.w};
#pragma unroll
            for (int i = 0; i < 8; i++)
#pragma unroll
                for (int j = 0; j < 8; j++)
                    acc[i][j] += a[i] * b[j];
        }
        __syncthreads();
    }

    const int m0 = aRow + ty * 8;
    const int n0 = bRow + tx * 8;

    if (mode == 0) {
#pragma unroll
        for (int i = 0; i < 8; i++) {
            float4 c0 = make_float4(acc[i][0], acc[i][1], acc[i][2], acc[i][3]);
            float4 c1 = make_float4(acc[i][4], acc[i][5], acc[i][6], acc[i][7]);
            *(float4*)&Cout[(size_t)(m0 + i) * DM + n0]     = c0;
            *(float4*)&Cout[(size_t)(m0 + i) * DM + n0 + 4] = c1;
        }
        return;
    }

    float* dst = (which == 0) ? g_q : (which == 1) ? g_k : g_v;
    const int h = n0 >> 6;          // 8 cols never cross a head boundary
    const int dbase = n0 & 63;

    if (mode == 2) {
#pragma unroll
        for (int i = 0; i < 8; i++) {
            int m = m0 + i;
            int b = m >> 11;            // / SEQ
            int s = m & (SEQ - 1);
            size_t idx = (((size_t)(b * NH + h)) * SEQ + s) * DH + dbase;
            *(float4*)&dst[idx]     = make_float4(acc[i][0], acc[i][1], acc[i][2], acc[i][3]);
            *(float4*)&dst[idx + 4] = make_float4(acc[i][4], acc[i][5], acc[i][6], acc[i][7]);
        }
        return;
    }

    // mode 1: RoPE. Columns come in (even, odd) interleaved pairs.
    float invf[4];
#pragma unroll
    for (int jp = 0; jp < 4; jp++) {
        int dd = dbase + 2 * jp;    // even index within head
        invf[jp] = (float)exp((double)dd * -0.14391156831212787);  // ln(1e4)/64
    }
#pragma unroll
    for (int i = 0; i < 8; i++) {
        int m = m0 + i;
        int b = m >> 11;
        int s = m & (SEQ - 1);
        float p = (float)pos[s];
        size_t idx = (((size_t)(b * NH + h)) * SEQ + s) * DH + dbase;
#pragma unroll
        for (int jp = 0; jp < 4; jp++) {
            float ang = p * invf[jp];
            float sn, cs;
            sincosf(ang, &sn, &cs);
            float e = acc[i][2 * jp];
            float o = acc[i][2 * jp + 1];
            dst[idx + 2 * jp]     = e * cs - o * sn;
            dst[idx + 2 * jp + 1] = e * sn + o * cs;
        }
    }
}

// ---------------------------------------------------------------------------
// Flash attention, fp32, causal. Per block: one (bh, 64-query tile).
// 256 threads, 4x4 microtiles over 64x64 score / output tiles.
// smem: Qs,Ks as [d][q] (pitch 68), Vs,Ps natural [k][d]/[q][k] (pitch 68).
// ---------------------------------------------------------------------------
#define FPITCH 68
#define FLASH_SMEM (4 * 64 * FPITCH * 4)   // 69632 bytes

__global__ __launch_bounds__(256) void flash_kernel()
{
    extern __shared__ float sm[];
    float* Qs = sm;
    float* Ks = sm + 64 * FPITCH;
    float* Vs = sm + 2 * 64 * FPITCH;
    float* Ps = sm + 3 * 64 * FPITCH;

    const int qt = blockIdx.x;
    const int bh = blockIdx.y;
    const int tid = threadIdx.x;
    const int tx = tid & 15;
    const int ty = tid >> 4;
    const int qbase = qt * 64;

    const float* Qg = g_q + (size_t)bh * SEQ * DH;
    const float* Kg = g_k + (size_t)bh * SEQ * DH;
    const float* Vg = g_v + (size_t)bh * SEQ * DH;

    // Load Q tile transposed: Qs[d][q]
#pragma unroll
    for (int j = 0; j < 4; j++) {
        int f = tid + j * 256;          // 1024 float4
        int r = f >> 4;                 // q row 0..63
        int d4 = (f & 15) << 2;
        float4 qv = *(const float4*)&Qg[(size_t)(qbase + r) * DH + d4];
        Qs[(d4 + 0) * FPITCH + r] = qv.x;
        Qs[(d4 + 1) * FPITCH + r] = qv.y;
        Qs[(d4 + 2) * FPITCH + r] = qv.z;
        Qs[(d4 + 3) * FPITCH + r] = qv.w;
    }

    float o[4][4];
    float mrun[4], lrun[4];
#pragma unroll
    for (int r = 0; r < 4; r++) {
        mrun[r] = -1e30f;
        lrun[r] = 0.0f;
#pragma unroll
        for (int c = 0; c < 4; c++) o[r][c] = 0.0f;
    }

    for (int kt = 0; kt <= qt; kt++) {
        const int kbase = kt * 64;
        // Load K transposed, V natural
#pragma unroll
        for (int j = 0; j < 4; j++) {
            int f = tid + j * 256;
            int r = f >> 4;
            int d4 = (f & 15) << 2;
            float4 kv = *(const float4*)&Kg[(size_t)(kbase + r) * DH + d4];
            Ks[(d4 + 0) * FPITCH + r] = kv.x;
            Ks[(d4 + 1) * FPITCH + r] = kv.y;
            Ks[(d4 + 2) * FPITCH + r] = kv.z;
            Ks[(d4 + 3) * FPITCH + r] = kv.w;
            float4 vv = *(const float4*)&Vg[(size_t)(kbase + r) * DH + d4];
            *(float4*)&Vs[r * FPITCH + d4] = vv;
        }
        __syncthreads();

        // S = Q K^T for this tile (4x4 per thread)
        float s[4][4];
#pragma unroll
        for (int r = 0; r < 4; r++)
#pragma unroll
            for (int c = 0; c < 4; c++) s[r][c] = 0.0f;

#pragma unroll
        for (int kk = 0; kk < 64; kk++) {
            float4 q4 = *(const float4*)&Qs[kk * FPITCH + ty * 4];
            float4 k4 = *(const float4*)&Ks[kk * FPITCH + tx * 4];
            float qa[4] = {q4.x, q4.y, q4.z, q4.w};
            float ka[4] = {k4.x, k4.y, k4.z, k4.w};
#pragma unroll
            for (int r = 0; r < 4; r++)
#pragma unroll
                for (int c = 0; c < 4; c++)
                    s[r][c] += qa[r] * ka[c];
        }

        // Online softmax update, per row
#pragma unroll
        for (int r = 0; r < 4; r++) {
            int qa_idx = qbase + ty * 4 + r;
            float mx = -1e30f;
#pragma unroll
            for (int c = 0; c < 4; c++) {
                int ka_idx = kbase + tx * 4 + c;
                float sv = s[r][c] * 0.125f;
                if (ka_idx > qa_idx) sv = -1e30f;
                s[r][c] = sv;
                mx = fmaxf(mx, sv);
            }
#pragma unroll
            for (int msk = 1; msk < 16; msk <<= 1)
                mx = fmaxf(mx, __shfl_xor_sync(0xffffffffu, mx, msk));
            float mnew = fmaxf(mrun[r], mx);
            float fac = expf(mrun[r] - mnew);
            mrun[r] = mnew;
            float rs = 0.0f;
#pragma unroll
            for (int c = 0; c < 4; c++) {
                float pv = expf(s[r][c] - mnew);
                s[r][c] = pv;
                rs += pv;
            }
#pragma unroll
            for (int msk = 1; msk < 16; msk <<= 1)
                rs += __shfl_xor_sync(0xffffffffu, rs, msk);
            lrun[r] = lrun[r] * fac + rs;
#pragma unroll
            for (int c = 0; c < 4; c++) o[r][c] *= fac;
            *(float4*)&Ps[(ty * 4 + r) * FPITCH + tx * 4] =
                make_float4(s[r][0], s[r][1], s[r][2], s[r][3]);
        }
        __syncthreads();

        // O += P V  (4x4 per thread)
#pragma unroll
        for (int kk = 0; kk < 64; kk++) {
            float4 v4 = *(const float4*)&Vs[kk * FPITCH + tx * 4];
#pragma unroll
            for (int r = 0; r < 4; r++) {
                float pr = Ps[(ty * 4 + r) * FPITCH + kk];
                o[r][0] += pr * v4.x;
                o[r][1] += pr * v4.y;
                o[r][2] += pr * v4.z;
                o[r][3] += pr * v4.w;
            }
        }
        __syncthreads();
    }

    // Write normalized output to g_attn in [b][s][h*64+d] layout
    const int b = bh >> 4;
    const int h = bh & 15;
#pragma unroll
    for (int r = 0; r < 4; r++) {
        float inv = 1.0f / lrun[r];
        int sa = qbase + ty * 4 + r;
        size_t idx = ((size_t)b * SEQ + sa) * DM + h * 64 + tx * 4;
        *(float4*)&g_attn[idx] =
            make_float4(o[r][0] * inv, o[r][1] * inv, o[r][2] * inv, o[r][3] * inv);
    }
}

// ---------------------------------------------------------------------------
extern "C" void kernel_launch(void* const* d_in, const int* in_sizes, int n_in,
                              void* d_out, int out_size)
{
    const float* x  = (const float*)d_in[0];
    const int* pos  = (const int*)d_in[1];
    const float* wq = (const float*)d_in[2];
    const float* wk = (const float*)d_in[3];
    const float* wv = (const float*)d_in[4];
    const float* wo = (const float*)d_in[5];
    float* out = (float*)d_out;

    dim3 gemm_grid(DM / 128, MTOT / 128);   // (8, 32)

    gemm_nt_kernel<<<gemm_grid, 256>>>(x, wq, pos, nullptr, 1, 0);  // Q + RoPE
    gemm_nt_kernel<<<gemm_grid, 256>>>(x, wk, pos, nullptr, 1, 1);  // K + RoPE
    gemm_nt_kernel<<<gemm_grid, 256>>>(x, wv, pos, nullptr, 2, 2);  // V

    cudaFuncSetAttribute(flash_kernel,
                         cudaFuncAttributeMaxDynamicSharedMemorySize, FLASH_SMEM);
    flash_kernel<<<dim3(SEQ / 64, BATCH * NH), 256, FLASH_SMEM>>>();

    gemm_nt_kernel<<<gemm_grid, 256>>>(nullptr, wo, pos, out, 0, 3); // O proj
}

// round 17
// speedup vs baseline: 1.5384x; 1.5384x over previous
#include <cuda_runtime.h>
#include <cuda_bf16.h>
#include <stdint.h>
#include <math.h>

#define BATCH 2
#define SEQ 2048
#define DM 1024
#define NH 16
#define DH 64
#define MTOT (BATCH * SEQ)   // 4096

// ---------------------------------------------------------------------------
// Scratch (allocation-free rule: __device__ globals)
// ---------------------------------------------------------------------------
__device__ float g_q[BATCH * NH * SEQ * DH];     // [bh][s][d]
__device__ float g_k[BATCH * NH * SEQ * DH];
__device__ float g_v[BATCH * NH * SEQ * DH];
__device__ float g_attn[BATCH * SEQ * DM];       // [b][s][h*64+d]

__device__ __nv_bfloat16 g_xhi[MTOT * DM];       // A operand hi/lo (x, later attn)
__device__ __nv_bfloat16 g_xlo[MTOT * DM];
__device__ __nv_bfloat16 g_whi[DM * DM];         // W operand hi/lo (reused per GEMM)
__device__ __nv_bfloat16 g_wlo[DM * DM];
__device__ float g_invf[32];                     // RoPE inverse frequencies

// ---------------------------------------------------------------------------
// PTX wrappers (all plain sm_80+ instructions, no arch-suffix features)
// ---------------------------------------------------------------------------
__device__ __forceinline__ uint32_t smem_u32(const void* p) {
    uint32_t a;
    asm("{ .reg .u64 t; cvta.to.shared.u64 t, %1; cvt.u32.u64 %0, t; }"
        : "=r"(a) : "l"(p));
    return a;
}

__device__ __forceinline__ void ldsm_x4(uint32_t* r, uint32_t addr) {
    asm volatile("ldmatrix.sync.aligned.m8n8.x4.shared.b16 {%0,%1,%2,%3}, [%4];"
        : "=r"(r[0]), "=r"(r[1]), "=r"(r[2]), "=r"(r[3]) : "r"(addr));
}

__device__ __forceinline__ void ldsm_x2(uint32_t* r, uint32_t addr) {
    asm volatile("ldmatrix.sync.aligned.m8n8.x2.shared.b16 {%0,%1}, [%2];"
        : "=r"(r[0]), "=r"(r[1]) : "r"(addr));
}

__device__ __forceinline__ void mma16816(float* d, const uint32_t* a, const uint32_t* b) {
    asm volatile(
        "mma.sync.aligned.m16n8k16.row.col.f32.bf16.bf16.f32 "
        "{%0,%1,%2,%3}, {%4,%5,%6,%7}, {%8,%9}, {%0,%1,%2,%3};"
        : "+f"(d[0]), "+f"(d[1]), "+f"(d[2]), "+f"(d[3])
        : "r"(a[0]), "r"(a[1]), "r"(a[2]), "r"(a[3]), "r"(b[0]), "r"(b[1]));
}

// ---------------------------------------------------------------------------
// Init / conversion kernels
// ---------------------------------------------------------------------------
__global__ void rope_init_kernel() {
    int i = threadIdx.x;
    if (i < 32)
        g_invf[i] = (float)exp((double)(2 * i) * -0.14391156831212787); // -ln(1e4)/64
}

__global__ void split_kernel(const float* __restrict__ src,
                             __nv_bfloat16* __restrict__ hi,
                             __nv_bfloat16* __restrict__ lo, int n) {
    int i = blockIdx.x * blockDim.x + threadIdx.x;
    if (i < n) {
        float v = src[i];
        __nv_bfloat16 h = __float2bfloat16(v);
        hi[i] = h;
        lo[i] = __float2bfloat16(v - __bfloat162float(h));
    }
}

// ---------------------------------------------------------------------------
// HMMA GEMM: C[m,n] = sum_k A[m,k]*W[n,k], M=4096, N=K=1024, fp32-accurate via
// 3-term bf16 split (AhiBhi + AhiBlo + AloBhi) on mma.sync.m16n8k16.
// CTA 128x128, 8 warps (2x4), warp tile 64x32, k-step 64.
// SMEM tiles pitch 72 bf16 (144B rows) -> conflict-free ldmatrix, no swizzle.
// mode 0: row-major write to Cout; mode 1: headed+RoPE (Q/K); mode 2: headed (V).
// ---------------------------------------------------------------------------
#define PITCH 72
#define TILE_B (128 * PITCH * 2)        // 18432 bytes per tile
#define OFF_AHI 0
#define OFF_ALO TILE_B
#define OFF_BHI (2 * TILE_B)
#define OFF_BLO (3 * TILE_B)
#define GEMM_SMEM (4 * TILE_B)          // 73728 bytes

__global__ __launch_bounds__(256) void gemm_mma_kernel(
    const __nv_bfloat16* __restrict__ Ahi, const __nv_bfloat16* __restrict__ Alo,
    const __nv_bfloat16* __restrict__ Bhi, const __nv_bfloat16* __restrict__ Blo,
    const int* __restrict__ pos, float* __restrict__ Cout,
    int mode, int which)
{
    extern __shared__ __align__(16) char smem[];
    const uint32_t sb = smem_u32(smem);
    const int tid = threadIdx.x;
    const int wid = tid >> 5;
    const int lane = tid & 31;
    const int warp_m = wid & 1;          // 0..1  -> 64 rows each
    const int warp_n = wid >> 1;         // 0..3  -> 32 cols each

    const int aRow = blockIdx.y * 128;
    const int bRow = blockIdx.x * 128;

    float acc[4][4][4];
#pragma unroll
    for (int i = 0; i < 4; i++)
#pragma unroll
        for (int j = 0; j < 4; j++)
#pragma unroll
            for (int c = 0; c < 4; c++) acc[i][j][c] = 0.0f;

    // ldmatrix per-lane base offsets (bytes)
    // A (.x4): matrix g = lane/8: row = m0 + (g&1)*8 + lane%8, col = k16 + (g>>1)*8
    const int rowA = warp_m * 64 + ((lane >> 3) & 1) * 8 + (lane & 7);
    const uint32_t offA = (uint32_t)(rowA * PITCH + (lane >> 4) * 8) * 2;  // +i*16*PITCH*2 +k16*32
    // B (.x2): lanes 0-15: matrix g = l/8: row n = n0 + l%8, col = k16 + g*8
    const int ln = lane & 15;
    const int rowB = warp_n * 32 + (ln & 7);
    const uint32_t offB = (uint32_t)(rowB * PITCH + ((ln >> 3) & 1) * 8) * 2; // +j*8*PITCH*2 +k16*32

    const __nv_bfloat16* srcA[2] = {Ahi + (size_t)aRow * DM, Alo + (size_t)aRow * DM};
    const __nv_bfloat16* srcB[2] = {Bhi + (size_t)bRow * DM, Blo + (size_t)bRow * DM};

    for (int k0 = 0; k0 < DM; k0 += 64) {
        // Stage 4 tiles of 128 rows x 64 bf16 into smem (pitch 72)
#pragma unroll
        for (int t = 0; t < 4; t++) {
            const __nv_bfloat16* src = (t < 2) ? srcA[t] : srcB[t - 2];
            const uint32_t base = t * TILE_B;
#pragma unroll
            for (int jj = 0; jj < 4; jj++) {
                int f = tid + jj * 256;         // 0..1023
                int r = f >> 3;                 // row 0..127
                int c8 = f & 7;                 // 8-elem chunk
                uint4 v = *(const uint4*)(src + (size_t)r * DM + k0 + c8 * 8);
                *(uint4*)(smem + base + (r * PITCH + c8 * 8) * 2) = v;
            }
        }
        __syncthreads();

#pragma unroll
        for (int k16 = 0; k16 < 4; k16++) {
            uint32_t ah[4][4], al[4][4];
            uint32_t bh[4][2], bl[4][2];
#pragma unroll
            for (int i = 0; i < 4; i++) {
                uint32_t o = offA + i * (16 * PITCH * 2) + k16 * 32;
                ldsm_x4(ah[i], sb + OFF_AHI + o);
                ldsm_x4(al[i], sb + OFF_ALO + o);
            }
#pragma unroll
            for (int j = 0; j < 4; j++) {
                uint32_t o = offB + j * (8 * PITCH * 2) + k16 * 32;
                ldsm_x2(bh[j], sb + OFF_BHI + o);
                ldsm_x2(bl[j], sb + OFF_BLO + o);
            }
#pragma unroll
            for (int i = 0; i < 4; i++)
#pragma unroll
                for (int j = 0; j < 4; j++)
                    mma16816(acc[i][j], ah[i], bh[j]);
#pragma unroll
            for (int i = 0; i < 4; i++)
#pragma unroll
                for (int j = 0; j < 4; j++)
                    mma16816(acc[i][j], ah[i], bl[j]);
#pragma unroll
            for (int i = 0; i < 4; i++)
#pragma unroll
                for (int j = 0; j < 4; j++)
                    mma16816(acc[i][j], al[i], bh[j]);
        }
        __syncthreads();
    }

    // ------------------------------------------------------------------
    // Epilogue. Acc frag: c0=D[m][n], c1=D[m][n+1], c2=D[m+8][n], c3=D[m+8][n+1]
    // with m = mBase + lane/4, n = nBase + 2*(lane%4)  (n always even).
    // ------------------------------------------------------------------
    const int tq = lane >> 2;
    const int n2 = (lane & 3) * 2;
    float* dst = (which == 0) ? g_q : (which == 1) ? g_k : g_v;

#pragma unroll
    for (int i = 0; i < 4; i++) {
        int m1 = aRow + warp_m * 64 + i * 16 + tq;
        int m2 = m1 + 8;

        if (mode == 0) {
#pragma unroll
            for (int j = 0; j < 4; j++) {
                int n_g = bRow + warp_n * 32 + j * 8 + n2;
                *(float2*)&Cout[(size_t)m1 * DM + n_g] = make_float2(acc[i][j][0], acc[i][j][1]);
                *(float2*)&Cout[(size_t)m2 * DM + n_g] = make_float2(acc[i][j][2], acc[i][j][3]);
            }
            continue;
        }

        int b1 = m1 >> 11, s1 = m1 & (SEQ - 1);
        int b2 = m2 >> 11, s2 = m2 & (SEQ - 1);

        if (mode == 2) {
#pragma unroll
            for (int j = 0; j < 4; j++) {
                int n_g = bRow + warp_n * 32 + j * 8 + n2;
                int h = n_g >> 6, d = n_g & 63;
                *(float2*)&dst[(((size_t)(b1 * NH + h)) * SEQ + s1) * DH + d] =
                    make_float2(acc[i][j][0], acc[i][j][1]);
                *(float2*)&dst[(((size_t)(b2 * NH + h)) * SEQ + s2) * DH + d] =
                    make_float2(acc[i][j][2], acc[i][j][3]);
            }
            continue;
        }

        // mode 1: RoPE — (c0,c1) and (c2,c3) are (even,odd) pairs in-thread.
        float p1 = (float)pos[s1];
        float p2 = (float)pos[s2];
#pragma unroll
        for (int j = 0; j < 4; j++) {
            int n_g = bRow + warp_n * 32 + j * 8 + n2;
            int h = n_g >> 6, d = n_g & 63;
            float invf = g_invf[d >> 1];
            float sn1, cs1, sn2, cs2;
            sincosf(p1 * invf, &sn1, &cs1);
            sincosf(p2 * invf, &sn2, &cs2);
            float e1 = acc[i][j][0], o1 = acc[i][j][1];
            float e2 = acc[i][j][2], o2 = acc[i][j][3];
            *(float2*)&dst[(((size_t)(b1 * NH + h)) * SEQ + s1) * DH + d] =
                make_float2(e1 * cs1 - o1 * sn1, e1 * sn1 + o1 * cs1);
            *(float2*)&dst[(((size_t)(b2 * NH + h)) * SEQ + s2) * DH + d] =
                make_float2(e2 * cs2 - o2 * sn2, e2 * sn2 + o2 * cs2);
        }
    }
}

// ---------------------------------------------------------------------------
// Flash attention, fp32, causal (__expf + longest-tile-first order)
// ---------------------------------------------------------------------------
#define FPITCH 68
#define FLASH_SMEM (4 * 64 * FPITCH * 4)   // 69632 bytes

__global__ __launch_bounds__(256) void flash_kernel()
{
    extern __shared__ float sm[];
    float* Qs = sm;
    float* Ks = sm + 64 * FPITCH;
    float* Vs = sm + 2 * 64 * FPITCH;
    float* Ps = sm + 3 * 64 * FPITCH;

    const int qt = (gridDim.x - 1) - blockIdx.x;   // longest tiles first
    const int bh = blockIdx.y;
    const int tid = threadIdx.x;
    const int tx = tid & 15;
    const int ty = tid >> 4;
    const int qbase = qt * 64;

    const float* Qg = g_q + (size_t)bh * SEQ * DH;
    const float* Kg = g_k + (size_t)bh * SEQ * DH;
    const float* Vg = g_v + (size_t)bh * SEQ * DH;

#pragma unroll
    for (int j = 0; j < 4; j++) {
        int f = tid + j * 256;
        int r = f >> 4;
        int d4 = (f & 15) << 2;
        float4 qv = *(const float4*)&Qg[(size_t)(qbase + r) * DH + d4];
        Qs[(d4 + 0) * FPITCH + r] = qv.x;
        Qs[(d4 + 1) * FPITCH + r] = qv.y;
        Qs[(d4 + 2) * FPITCH + r] = qv.z;
        Qs[(d4 + 3) * FPITCH + r] = qv.w;
    }

    float o[4][4];
    float mrun[4], lrun[4];
#pragma unroll
    for (int r = 0; r < 4; r++) {
        mrun[r] = -1e30f;
        lrun[r] = 0.0f;
#pragma unroll
        for (int c = 0; c < 4; c++) o[r][c] = 0.0f;
    }

    for (int kt = 0; kt <= qt; kt++) {
        const int kbase = kt * 64;
#pragma unroll
        for (int j = 0; j < 4; j++) {
            int f = tid + j * 256;
            int r = f >> 4;
            int d4 = (f & 15) << 2;
            float4 kv = *(const float4*)&Kg[(size_t)(kbase + r) * DH + d4];
            Ks[(d4 + 0) * FPITCH + r] = kv.x;
            Ks[(d4 + 1) * FPITCH + r] = kv.y;
            Ks[(d4 + 2) * FPITCH + r] = kv.z;
            Ks[(d4 + 3) * FPITCH + r] = kv.w;
            float4 vv = *(const float4*)&Vg[(size_t)(kbase + r) * DH + d4];
            *(float4*)&Vs[r * FPITCH + d4] = vv;
        }
        __syncthreads();

        float s[4][4];
#pragma unroll
        for (int r = 0; r < 4; r++)
#pragma unroll
            for (int c = 0; c < 4; c++) s[r][c] = 0.0f;

#pragma unroll
        for (int kk = 0; kk < 64; kk++) {
            float4 q4 = *(const float4*)&Qs[kk * FPITCH + ty * 4];
            float4 k4 = *(const float4*)&Ks[kk * FPITCH + tx * 4];
            float qa[4] = {q4.x, q4.y, q4.z, q4.w};
            float ka[4] = {k4.x, k4.y, k4.z, k4.w};
#pragma unroll
            for (int r = 0; r < 4; r++)
#pragma unroll
                for (int c = 0; c < 4; c++)
                    s[r][c] += qa[r] * ka[c];
        }

#pragma unroll
        for (int r = 0; r < 4; r++) {
            int qa_idx = qbase + ty * 4 + r;
            float mx = -1e30f;
#pragma unroll
            for (int c = 0; c < 4; c++) {
                int ka_idx = kbase + tx * 4 + c;
                float sv = s[r][c] * 0.125f;
                if (ka_idx > qa_idx) sv = -1e30f;
                s[r][c] = sv;
                mx = fmaxf(mx, sv);
            }
#pragma unroll
            for (int msk = 1; msk < 16; msk <<= 1)
                mx = fmaxf(mx, __shfl_xor_sync(0xffffffffu, mx, msk));
            float mnew = fmaxf(mrun[r], mx);
            float fac = __expf(mrun[r] - mnew);
            mrun[r] = mnew;
            float rs = 0.0f;
#pragma unroll
            for (int c = 0; c < 4; c++) {
                float pv = __expf(s[r][c] - mnew);
                s[r][c] = pv;
                rs += pv;
            }
#pragma unroll
            for (int msk = 1; msk < 16; msk <<= 1)
                rs += __shfl_xor_sync(0xffffffffu, rs, msk);
            lrun[r] = lrun[r] * fac + rs;
#pragma unroll
            for (int c = 0; c < 4; c++) o[r][c] *= fac;
            *(float4*)&Ps[(ty * 4 + r) * FPITCH + tx * 4] =
                make_float4(s[r][0], s[r][1], s[r][2], s[r][3]);
        }
        __syncthreads();

#pragma unroll
        for (int kk = 0; kk < 64; kk++) {
            float4 v4 = *(const float4*)&Vs[kk * FPITCH + tx * 4];
#pragma unroll
            for (int r = 0; r < 4; r++) {
                float pr = Ps[(ty * 4 + r) * FPITCH + kk];
                o[r][0] += pr * v4.x;
                o[r][1] += pr * v4.y;
                o[r][2] += pr * v4.z;
                o[r][3] += pr * v4.w;
            }
        }
        __syncthreads();
    }

    const int b = bh >> 4;
    const int h = bh & 15;
#pragma unroll
    for (int r = 0; r < 4; r++) {
        float inv = 1.0f / lrun[r];
        int sa = qbase + ty * 4 + r;
        size_t idx = ((size_t)b * SEQ + sa) * DM + h * 64 + tx * 4;
        *(float4*)&g_attn[idx] =
            make_float4(o[r][0] * inv, o[r][1] * inv, o[r][2] * inv, o[r][3] * inv);
    }
}

// ---------------------------------------------------------------------------
extern "C" void kernel_launch(void* const* d_in, const int* in_sizes, int n_in,
                              void* d_out, int out_size)
{
    const float* x  = (const float*)d_in[0];
    const int* pos  = (const int*)d_in[1];
    const float* wq = (const float*)d_in[2];
    const float* wk = (const float*)d_in[3];
    const float* wv = (const float*)d_in[4];
    const float* wo = (const float*)d_in[5];
    float* out = (float*)d_out;

    __nv_bfloat16 *xhi, *xlo, *whi, *wlo;
    cudaGetSymbolAddress((void**)&xhi, g_xhi);
    cudaGetSymbolAddress((void**)&xlo, g_xlo);
    cudaGetSymbolAddress((void**)&whi, g_whi);
    cudaGetSymbolAddress((void**)&wlo, g_wlo);
    float* attn;
    cudaGetSymbolAddress((void**)&attn, g_attn);

    cudaFuncSetAttribute(gemm_mma_kernel,
                         cudaFuncAttributeMaxDynamicSharedMemorySize, GEMM_SMEM);
    cudaFuncSetAttribute(flash_kernel,
                         cudaFuncAttributeMaxDynamicSharedMemorySize, FLASH_SMEM);

    dim3 gemm_grid(DM / 128, MTOT / 128);   // (8, 32)
    const int NX = MTOT * DM;               // 4M
    const int NW = DM * DM;                 // 1M

    rope_init_kernel<<<1, 32>>>();
    split_kernel<<<(NX + 255) / 256, 256>>>(x, xhi, xlo, NX);

    split_kernel<<<(NW + 255) / 256, 256>>>(wq, whi, wlo, NW);
    gemm_mma_kernel<<<gemm_grid, 256, GEMM_SMEM>>>(xhi, xlo, whi, wlo, pos, nullptr, 1, 0);

    split_kernel<<<(NW + 255) / 256, 256>>>(wk, whi, wlo, NW);
    gemm_mma_kernel<<<gemm_grid, 256, GEMM_SMEM>>>(xhi, xlo, whi, wlo, pos, nullptr, 1, 1);

    split_kernel<<<(NW + 255) / 256, 256>>>(wv, whi, wlo, NW);
    gemm_mma_kernel<<<gemm_grid, 256, GEMM_SMEM>>>(xhi, xlo, whi, wlo, pos, nullptr, 2, 2);

    flash_kernel<<<dim3(SEQ / 64, BATCH * NH), 256, FLASH_SMEM>>>();

    split_kernel<<<(NX + 255) / 256, 256>>>(attn, xhi, xlo, NX);
    split_kernel<<<(NW + 255) / 256, 256>>>(wo, whi, wlo, NW);
    gemm_mma_kernel<<<gemm_grid, 256, GEMM_SMEM>>>(xhi, xlo, whi, wlo, pos, out, 0, 3);
}